// round 11
// baseline (speedup 1.0000x reference)
#include <cuda_runtime.h>

// Shapes (fixed)
#define B_   4
#define N_   8192
#define M2_  8192
#define M3_  4096
#define M4_  2048
#define MM_  4096
#define C_   32
#define BN_  (B_ * N_)

#define TPB   256
#define SPLIT 8
#define QPT   4
#define QPB   ((TPB / SPLIT) * QPT)   // 128 queries/block -> 256 blocks
#define TILE  2048
#define PAIRS (TILE / 2)

typedef unsigned long long ull;

#define INF_F   __int_as_float(0x7f800000)
#define NINF_F  __int_as_float(0xff800000)
#define NEG2X   0xC0000000C0000000ull   // (-2.0f, -2.0f)
#define DELTA   8e-3f                    // rounding-slack (abs, d2 units)

// scratch (no allocations allowed)
__device__ float d_v[96];
__device__ float d_g[B_ * (M2_ + M3_ + M4_)];

// ---------------------------------------------------------------------------
// packed f32x2 helpers (only add/mul/fma exist in PTX; min/max are scalar)
__device__ __forceinline__ ull f2pack(float lo, float hi) {
    ull r; asm("mov.b64 %0,{%1,%2};" : "=l"(r) : "f"(lo), "f"(hi)); return r;
}
__device__ __forceinline__ void f2unpack(float& lo, float& hi, ull v) {
    asm("mov.b64 {%0,%1},%2;" : "=f"(lo), "=f"(hi) : "l"(v));
}
__device__ __forceinline__ ull add2(ull a, ull b) {
    ull r; asm("add.rn.f32x2 %0,%1,%2;" : "=l"(r) : "l"(a), "l"(b)); return r;
}
__device__ __forceinline__ ull mul2(ull a, ull b) {
    ull r; asm("mul.rn.f32x2 %0,%1,%2;" : "=l"(r) : "l"(a), "l"(b)); return r;
}
__device__ __forceinline__ ull fma2(ull a, ull b, ull c) {
    ull r; asm("fma.rn.f32x2 %0,%1,%2,%3;" : "=l"(r) : "l"(a), "l"(b), "l"(c)); return r;
}

// reference-order squared norm: (x*x + y*y) + z*z
__device__ __forceinline__ float norm2_ref(float x, float y, float z) {
    return __fadd_rn(__fadd_rn(__fmul_rn(x, x), __fmul_rn(y, y)), __fmul_rn(z, z));
}

// exact reference rounding: d2 = (Sq + Sk) - 2*(qx*kx + qy*ky + qz*kz)
__device__ __forceinline__ ull d2pair(ull x2, ull y2, ull z2, ull w2,
                                      ull qx, ull qy, ull qz, ull sq) {
    ull t  = add2(sq, w2);
    ull cr = mul2(qx, x2);
    cr = fma2(qy, y2, cr);
    cr = fma2(qz, z2, cr);
    return fma2((ull)NEG2X, cr, t);
}

// ---------------------------------------------------------------------------
__global__ void compute_v_kernel(const float* __restrict__ w_fc,
                                 const float* __restrict__ w_cls) {
    int k = threadIdx.x;
    if (k < 96) {
        float acc = 0.f;
#pragma unroll
        for (int j = 0; j < 64; ++j)
            acc += w_cls[j] * w_fc[j * 96 + k];
        d_v[k] = acc;
    }
}

__global__ void compute_g_kernel(const float* __restrict__ f2,
                                 const float* __restrict__ f3,
                                 const float* __restrict__ f4) {
    int warp = (blockIdx.x * blockDim.x + threadIdx.x) >> 5;
    int lane = threadIdx.x & 31;
    const int NG2 = B_ * M2_, NG3 = B_ * M3_, NG4 = B_ * M4_;
    const float* src;
    int base, voff, p = warp;
    if (p < NG2)                  { src = f2; base = 0;          voff = 0;  }
    else if (p < NG2 + NG3)       { p -= NG2; src = f3; base = NG2;        voff = 32; }
    else if (p < NG2 + NG3 + NG4) { p -= NG2 + NG3; src = f4; base = NG2 + NG3; voff = 64; }
    else return;
    float x = src[p * C_ + lane] * d_v[voff + lane];
#pragma unroll
    for (int o = 16; o; o >>= 1) x += __shfl_xor_sync(0xffffffffu, x, o);
    if (lane == 0) d_g[base + p] = x;
}

// ---------------------------------------------------------------------------
struct Q4 { ull x[QPT], y[QPT], z[QPT], s2[QPT]; float sq[QPT]; };

// MODE 0: pass1  (s_b.y = -0.5*Sk, s_h unused)
// MODE 1: pass2  (s_b.y =  Sk,     s_h = -0.5*Sk)
// MODE 2: mask   (s_b.y =  Sk)
template <int MODE>
__device__ __forceinline__ void fill_tile(const float* __restrict__ coord, int t0,
                                          ulonglong2* s_a, ulonglong2* s_b,
                                          ull* s_h, int tid) {
    for (int p = tid; p < PAIRS; p += TPB) {
        const float* c = coord + (size_t)(t0 + 2 * p) * 3;
        float x0 = c[0], y0 = c[1], z0 = c[2];
        float x1 = c[3], y1 = c[4], z1 = c[5];
        float n0 = norm2_ref(x0, y0, z0), n1 = norm2_ref(x1, y1, z1);
        s_a[p] = make_ulonglong2(f2pack(x0, x1), f2pack(y0, y1));
        if (MODE == 0)
            s_b[p] = make_ulonglong2(f2pack(z0, z1), f2pack(-0.5f * n0, -0.5f * n1));
        else
            s_b[p] = make_ulonglong2(f2pack(z0, z1), f2pack(n0, n1));
        if (MODE == 1) s_h[p] = f2pack(-0.5f * n0, -0.5f * n1);
    }
}

// merge two descending value-triples keeping 3 largest (exact selects)
__device__ __forceinline__ void mrg3max(float& r0, float& r1, float& r2,
                                        float b0, float b1, float b2) {
    float t  = fminf(r0, b0);
    float m0 = fmaxf(r0, b0);
    float m1 = fmaxf(r1, b1);
    float n1 = fmaxf(t, m1);
    float n2 = fmaxf(fminf(m1, t), fmaxf(r2, b2));
    r0 = m0; r1 = n1; r2 = n2;
}

// ---------------------------------------------------------------------------
// PASS 1: lower bound on the 3rd-largest s' = q.k - 0.5|k|^2 (larger = closer)
template <int M>
__device__ __forceinline__ void nn_threshold(
    const float* __restrict__ coord, const Q4& q, int tid, int split,
    ulonglong2* s_a, ulonglong2* s_b, ull* s_h, float* thrS) {
    float T0[QPT], T1[QPT], T2[QPT];
#pragma unroll
    for (int j = 0; j < QPT; ++j) { T0[j] = NINF_F; T1[j] = NINF_F; T2[j] = NINF_F; }

    for (int t0 = 0; t0 < M; t0 += TILE) {
        __syncthreads();
        fill_tile<0>(coord, t0, s_a, s_b, s_h, tid);
        __syncthreads();
#pragma unroll 4
        for (int i = 0; i < PAIRS / SPLIT; ++i) {
            int loc = (i << 3) | split;
            ulonglong2 a = s_a[loc];
            ulonglong2 b = s_b[loc];
#pragma unroll
            for (int j = 0; j < QPT; ++j) {
                ull s = fma2(q.x[j], a.x, b.y);   // q.x*kx + (-0.5*Sk)
                s = fma2(q.y[j], a.y, s);
                s = fma2(q.z[j], b.x, s);
                float lo, hi; f2unpack(lo, hi, s);
                float m = fmaxf(lo, hi);          // pair-collapse (upper-bnd safe)
                T2[j] = fmaxf(T2[j], fminf(T1[j], m));
                T1[j] = fmaxf(T1[j], fminf(T0[j], m));
                T0[j] = fmaxf(T0[j], m);
            }
        }
    }
#pragma unroll
    for (int j = 0; j < QPT; ++j) {
        float a0 = T0[j], a1 = T1[j], a2 = T2[j];
#pragma unroll
        for (int off = 1; off < SPLIT; off <<= 1) {
            float b0 = __shfl_xor_sync(0xffffffffu, a0, off);
            float b1 = __shfl_xor_sync(0xffffffffu, a1, off);
            float b2 = __shfl_xor_sync(0xffffffffu, a2, off);
            mrg3max(a0, a1, a2, b0, b1, b2);
        }
        thrS[j] = a2;   // <= true 3rd-largest s'
    }
}

// ---------------------------------------------------------------------------
__device__ __forceinline__ bool ltlex(float ad, int ai, float bd, int bi) {
    return (ad < bd) || (ad == bd && ai < bi);
}

__device__ __forceinline__ void ins3lex(float d, int i,
                                        float& d0, float& d1, float& d2,
                                        int& i0, int& i1, int& i2) {
    if (ltlex(d, i, d2, i2)) {
        if (ltlex(d, i, d1, i1)) {
            d2 = d1; i2 = i1;
            if (ltlex(d, i, d0, i0)) { d1 = d0; i1 = i0; d0 = d; i0 = i; }
            else                     { d1 = d;  i1 = i; }
        } else { d2 = d; i2 = i; }
    }
}

__device__ __forceinline__ void merge3lex(
    float& a0, float& a1, float& a2, int& i0, int& i1, int& i2,
    float b0, float b1, float b2, int j0, int j1, int j2) {
    bool t = ltlex(a0, i0, b0, j0);
    float o0 = t ? a0 : b0; int oi0 = t ? i0 : j0;
    float x0 = t ? a1 : b1; int xi0 = t ? i1 : j1;
    float x1 = t ? a2 : b2; int xi1 = t ? i2 : j2;
    float y0 = t ? b0 : a0; int yi0 = t ? j0 : i0;
    float y1 = t ? b1 : a1; int yi1 = t ? j1 : i1;
    bool u = ltlex(x0, xi0, y0, yi0);
    float o1 = u ? x0 : y0; int oi1 = u ? xi0 : yi0;
    float z0 = u ? x1 : y1; int zi0 = u ? xi1 : yi1;
    float z1 = u ? y0 : x0; int zi1 = u ? yi0 : xi0;
    bool v = ltlex(z0, zi0, z1, zi1);
    a0 = o0; a1 = o1; a2 = v ? z0 : z1;
    i0 = oi0; i1 = oi1; i2 = v ? zi0 : zi1;
}

// ---------------------------------------------------------------------------
// PASS 2: gate with identical-rounding s'; exact ref-d2 + lex top-3 on hits
template <int M>
__device__ __forceinline__ void nn_select(
    const float* __restrict__ coord, const float* __restrict__ gsrc,
    const Q4& q, const float* thrS, int tid, int split,
    ulonglong2* s_a, ulonglong2* s_b, ull* s_h, float* pred) {
    float thrD[QPT], gate[QPT];
#pragma unroll
    for (int j = 0; j < QPT; ++j) {
        thrD[j] = q.sq[j] - 2.f * thrS[j] + DELTA;
        gate[j] = thrS[j] - DELTA;
    }
    float D0[QPT], D1[QPT], D2[QPT];
    int   I0[QPT], I1[QPT], I2[QPT];
#pragma unroll
    for (int j = 0; j < QPT; ++j) {
        D0[j] = D1[j] = D2[j] = INF_F;
        I0[j] = I1[j] = I2[j] = 0x7fffffff;
    }

    for (int t0 = 0; t0 < M; t0 += TILE) {
        __syncthreads();
        fill_tile<1>(coord, t0, s_a, s_b, s_h, tid);
        __syncthreads();
#pragma unroll 4
        for (int i = 0; i < PAIRS / SPLIT; ++i) {
            int loc = (i << 3) | split;
            ulonglong2 a = s_a[loc];
            ulonglong2 b = s_b[loc];
            ull h = s_h[loc];
#pragma unroll
            for (int j = 0; j < QPT; ++j) {
                ull s = fma2(q.x[j], a.x, h);     // bitwise == pass1's s'
                s = fma2(q.y[j], a.y, s);
                s = fma2(q.z[j], b.x, s);
                float lo, hi; f2unpack(lo, hi, s);
                if (fmaxf(lo, hi) >= gate[j]) {   // rare (~2% of warp-iters)
                    ull dd = d2pair(a.x, a.y, b.x, b.y,
                                    q.x[j], q.y[j], q.z[j], q.s2[j]);
                    float da, db; f2unpack(da, db, dd);
                    int ib = t0 + 2 * loc;
                    if (da <= thrD[j])
                        ins3lex(da, ib, D0[j], D1[j], D2[j], I0[j], I1[j], I2[j]);
                    if (db <= thrD[j])
                        ins3lex(db, ib + 1, D0[j], D1[j], D2[j], I0[j], I1[j], I2[j]);
                }
            }
        }
    }
#pragma unroll
    for (int j = 0; j < QPT; ++j) {
        float d0 = D0[j], d1 = D1[j], d2 = D2[j];
        int   i0 = I0[j], i1 = I1[j], i2 = I2[j];
#pragma unroll
        for (int off = 1; off < SPLIT; off <<= 1) {
            float b0 = __shfl_xor_sync(0xffffffffu, d0, off);
            float b1 = __shfl_xor_sync(0xffffffffu, d1, off);
            float b2 = __shfl_xor_sync(0xffffffffu, d2, off);
            int   j0 = __shfl_xor_sync(0xffffffffu, i0, off);
            int   j1 = __shfl_xor_sync(0xffffffffu, i1, off);
            int   j2 = __shfl_xor_sync(0xffffffffu, i2, off);
            merge3lex(d0, d1, d2, i0, i1, i2, b0, b1, b2, j0, j1, j2);
        }
        float g0 = __ldg(gsrc + i0);
        float g1 = __ldg(gsrc + i1);
        float g2 = __ldg(gsrc + i2);
        float c0 = fmaxf(d0, 0.f), c1 = fmaxf(d1, 0.f), c2 = fmaxf(d2, 0.f);
        float r0 = 1.f / (c0 + 1e-8f);
        float r1 = 1.f / (c1 + 1e-8f);
        float r2 = 1.f / (c2 + 1e-8f);
        float S  = __fadd_rn(__fadd_rn(r0, r1), r2);
        float w0 = r0 / S, w1 = r1 / S, w2 = r2 / S;
        pred[j] += __fadd_rn(__fadd_rn(__fmul_rn(w0, g0), __fmul_rn(w1, g1)),
                             __fmul_rn(w2, g2));
    }
}

// ---------------------------------------------------------------------------
// Mask: exact reference-rounded min of d2 (binary output: cannot approximate)
template <int M>
__device__ __forceinline__ void mask_min(
    const float* __restrict__ coord, const Q4& q, int tid, int split,
    ulonglong2* s_a, ulonglong2* s_b, ull* s_h, float* mind) {
    float mA[QPT], mB[QPT];
#pragma unroll
    for (int j = 0; j < QPT; ++j) { mA[j] = INF_F; mB[j] = INF_F; }

    for (int t0 = 0; t0 < M; t0 += TILE) {
        __syncthreads();
        fill_tile<2>(coord, t0, s_a, s_b, s_h, tid);
        __syncthreads();
#pragma unroll 4
        for (int i = 0; i < PAIRS / SPLIT; ++i) {
            int loc = (i << 3) | split;
            ulonglong2 a = s_a[loc];
            ulonglong2 b = s_b[loc];
#pragma unroll
            for (int j = 0; j < QPT; ++j) {
                ull dd = d2pair(a.x, a.y, b.x, b.y,
                                q.x[j], q.y[j], q.z[j], q.s2[j]);
                float da, db; f2unpack(da, db, dd);
                mA[j] = fminf(mA[j], da);
                mB[j] = fminf(mB[j], db);
            }
        }
    }
#pragma unroll
    for (int j = 0; j < QPT; ++j) {
        float m = fminf(mA[j], mB[j]);
#pragma unroll
        for (int off = 1; off < SPLIT; off <<= 1)
            m = fminf(m, __shfl_xor_sync(0xffffffffu, m, off));
        mind[j] = m;
    }
}

// ---------------------------------------------------------------------------
__global__ __launch_bounds__(TPB)
void height_compression_main(const float* __restrict__ pts,
                             const float* __restrict__ k2,
                             const float* __restrict__ k3,
                             const float* __restrict__ k4,
                             const float* __restrict__ mp,
                             float* __restrict__ out) {
    __shared__ ulonglong2 s_a[PAIRS];  // (x2, y2)
    __shared__ ulonglong2 s_b[PAIRS];  // (z2, w2)
    __shared__ ull        s_h[PAIRS];  // (-0.5*Sk) packed, pass2 only

    const int tid   = threadIdx.x;
    const int split = tid & (SPLIT - 1);
    const int qg    = tid >> 3;
    const int q0    = blockIdx.x * QPB + qg * QPT;
    const int b     = blockIdx.x >> 6;   // 64 blocks per batch (QPB=128)

    Q4 q;
#pragma unroll
    for (int j = 0; j < QPT; ++j) {
        float qx = pts[(q0 + j) * 3 + 0];
        float qy = pts[(q0 + j) * 3 + 1];
        float qz = pts[(q0 + j) * 3 + 2];
        q.x[j] = f2pack(qx, qx);
        q.y[j] = f2pack(qy, qy);
        q.z[j] = f2pack(qz, qz);
        float s = norm2_ref(qx, qy, qz);
        q.s2[j] = f2pack(s, s);
        q.sq[j] = s;
    }

    float pred[QPT] = {0.f, 0.f, 0.f, 0.f};
    float thrS[QPT];

    const float* c2 = k2 + (size_t)b * M2_ * 3;
    nn_threshold<M2_>(c2, q, tid, split, s_a, s_b, s_h, thrS);
    nn_select<M2_>(c2, d_g + (size_t)b * M2_, q, thrS, tid, split,
                   s_a, s_b, s_h, pred);

    const float* c3 = k3 + (size_t)b * M3_ * 3;
    nn_threshold<M3_>(c3, q, tid, split, s_a, s_b, s_h, thrS);
    nn_select<M3_>(c3, d_g + B_ * M2_ + (size_t)b * M3_, q, thrS, tid, split,
                   s_a, s_b, s_h, pred);

    const float* c4 = k4 + (size_t)b * M4_ * 3;
    nn_threshold<M4_>(c4, q, tid, split, s_a, s_b, s_h, thrS);
    nn_select<M4_>(c4, d_g + B_ * (M2_ + M3_) + (size_t)b * M4_, q, thrS,
                   tid, split, s_a, s_b, s_h, pred);

    float mind[QPT];
    mask_min<MM_>(mp + (size_t)b * MM_ * 3, q, tid, split, s_a, s_b, s_h, mind);

    if (split == 0) {
#pragma unroll
        for (int j = 0; j < QPT; ++j) {
            out[q0 + j] = pred[j];
            float md = sqrtf(fmaxf(mind[j], 0.f));   // ref: sqrt then < 0.5
            out[BN_ + q0 + j] = (md < 0.5f) ? 1.0f : 0.0f;
        }
    }
}

// ---------------------------------------------------------------------------
extern "C" void kernel_launch(void* const* d_in, const int* in_sizes, int n_in,
                              void* d_out, int out_size) {
    const float* pts  = (const float*)d_in[0];
    const float* k2   = (const float*)d_in[1];
    const float* f2   = (const float*)d_in[2];
    const float* k3   = (const float*)d_in[3];
    const float* f3   = (const float*)d_in[4];
    const float* k4   = (const float*)d_in[5];
    const float* f4   = (const float*)d_in[6];
    const float* mp   = (const float*)d_in[7];
    const float* wfc  = (const float*)d_in[8];
    const float* wcls = (const float*)d_in[9];

    compute_v_kernel<<<1, 96>>>(wfc, wcls);
    compute_g_kernel<<<(57344 * 32) / 256, 256>>>(f2, f3, f4);
    height_compression_main<<<BN_ / QPB, TPB>>>(pts, k2, k3, k4, mp,
                                                (float*)d_out);
}

// round 14
// speedup vs baseline: 1.2176x; 1.2176x over previous
#include <cuda_runtime.h>

// Shapes (fixed)
#define B_   4
#define N_   8192
#define M2_  8192
#define M3_  4096
#define M4_  2048
#define MM_  4096
#define C_   32
#define BN_  (B_ * N_)

#define TPB   256
#define SPLIT 8
#define QPT   4
#define QPB   ((TPB / SPLIT) * QPT)   // 128 queries/block -> 256 blocks
#define TILE  1024                    // candidates per smem tile (32KB total)

typedef unsigned long long ull;

#define INF_F   __int_as_float(0x7f800000)
#define NEG2X   0xC0000000C0000000ull   // (-2.0f, -2.0f)

// scratch (no allocations allowed)
__device__ float d_g[B_ * (M2_ + M3_ + M4_)];

// ---------------------------------------------------------------------------
// packed f32x2 helpers (lane-wise IEEE rn — bit-identical to scalar ops)
__device__ __forceinline__ ull f2pack(float lo, float hi) {
    ull r; asm("mov.b64 %0,{%1,%2};" : "=l"(r) : "f"(lo), "f"(hi)); return r;
}
__device__ __forceinline__ void f2unpack(float& lo, float& hi, ull v) {
    asm("mov.b64 {%0,%1},%2;" : "=f"(lo), "=f"(hi) : "l"(v));
}
__device__ __forceinline__ ull add2(ull a, ull b) {
    ull r; asm("add.rn.f32x2 %0,%1,%2;" : "=l"(r) : "l"(a), "l"(b)); return r;
}
__device__ __forceinline__ ull mul2(ull a, ull b) {
    ull r; asm("mul.rn.f32x2 %0,%1,%2;" : "=l"(r) : "l"(a), "l"(b)); return r;
}
__device__ __forceinline__ ull fma2(ull a, ull b, ull c) {
    ull r; asm("fma.rn.f32x2 %0,%1,%2,%3;" : "=l"(r) : "l"(a), "l"(b), "l"(c)); return r;
}

// reference-order squared norm: (x*x + y*y) + z*z
__device__ __forceinline__ float norm2_ref(float x, float y, float z) {
    return __fadd_rn(__fadd_rn(__fmul_rn(x, x), __fmul_rn(y, y)), __fmul_rn(z, z));
}

// ---------------------------------------------------------------------------
// Fused prep: v[96] per-block (redundant, cheap), then g[p] = feats[p,:].v_seg
// One warp per known point; 1024 threads/block -> 32 points/block.
__global__ __launch_bounds__(1024)
void compute_gv_kernel(const float* __restrict__ f2,
                       const float* __restrict__ f3,
                       const float* __restrict__ f4,
                       const float* __restrict__ w_fc,
                       const float* __restrict__ w_cls) {
    __shared__ float sv[96];
    int tid = threadIdx.x;
    if (tid < 96) {
        float acc = 0.f;
#pragma unroll
        for (int j = 0; j < 64; ++j)
            acc += w_cls[j] * w_fc[j * 96 + tid];
        sv[tid] = acc;
    }
    __syncthreads();

    int warp = blockIdx.x * 32 + (tid >> 5);
    int lane = tid & 31;
    const int NG2 = B_ * M2_, NG3 = B_ * M3_, NG4 = B_ * M4_;
    const float* src;
    int base, voff, p = warp;
    if (p < NG2)                  { src = f2; base = 0;          voff = 0;  }
    else if (p < NG2 + NG3)       { p -= NG2; src = f3; base = NG2;        voff = 32; }
    else if (p < NG2 + NG3 + NG4) { p -= NG2 + NG3; src = f4; base = NG2 + NG3; voff = 64; }
    else return;
    float x = src[p * C_ + lane] * sv[voff + lane];
#pragma unroll
    for (int o = 16; o; o >>= 1) x += __shfl_xor_sync(0xffffffffu, x, o);
    if (lane == 0) d_g[base + p] = x;
}

// ---------------------------------------------------------------------------
struct Q4 {
    ull x01, y01, z01, s01;   // queries 0,1 packed
    ull x23, y23, z23, s23;   // queries 2,3 packed
};

// Fill tile with pre-duplicated candidate data:
//   s_ab[c] = ((x,x),(y,y))   s_cd[c] = ((z,z),(Sk,Sk))
__device__ __forceinline__ void fill_tile(const float* __restrict__ coord, int t0,
                                          ulonglong2* s_ab, ulonglong2* s_cd,
                                          int tid) {
    for (int p = tid; p < TILE; p += TPB) {
        const float* c = coord + (size_t)(t0 + p) * 3;
        float x = c[0], y = c[1], z = c[2];
        float n = norm2_ref(x, y, z);
        s_ab[p] = make_ulonglong2(f2pack(x, x), f2pack(y, y));
        s_cd[p] = make_ulonglong2(f2pack(z, z), f2pack(n, n));
    }
}

// exact reference rounding: d2 = (Sq + Sk) - 2*(qx*kx + qy*ky + qz*kz)
// candidate duplicated in both lanes; two queries per packed op.
__device__ __forceinline__ ull d2q(ull kx, ull ky, ull kz, ull kw,
                                   ull qx, ull qy, ull qz, ull sq) {
    ull t  = add2(sq, kw);
    ull cr = mul2(qx, kx);
    cr = fma2(qy, ky, cr);
    cr = fma2(qz, kz, cr);
    return fma2((ull)NEG2X, cr, t);
}

// ---------------------------------------------------------------------------
// insert (d, idx) into ascending top-3 by strict value-< (candidates arrive in
// ascending index order => equivalent to top_k's lowest-index tie-break)
__device__ __forceinline__ void ins3(float d, int ib,
                                     float& d0, float& d1, float& d2,
                                     int& i0, int& i1, int& i2) {
    if (d < d1) {
        d2 = d1; i2 = i1;
        if (d < d0) { d1 = d0; i1 = i0; d0 = d; i0 = ib; }
        else        { d1 = d;  i1 = ib; }
    } else { d2 = d; i2 = ib; }
}

__device__ __forceinline__ bool ltlex(float ad, int ai, float bd, int bi) {
    return (ad < bd) || (ad == bd && ai < bi);
}

// merge two lex-sorted (d, idx) triples keeping 3 smallest
__device__ __forceinline__ void merge3lex(
    float& a0, float& a1, float& a2, int& i0, int& i1, int& i2,
    float b0, float b1, float b2, int j0, int j1, int j2) {
    bool t = ltlex(a0, i0, b0, j0);
    float o0 = t ? a0 : b0; int oi0 = t ? i0 : j0;
    float x0 = t ? a1 : b1; int xi0 = t ? i1 : j1;
    float x1 = t ? a2 : b2; int xi1 = t ? i2 : j2;
    float y0 = t ? b0 : a0; int yi0 = t ? j0 : i0;
    float y1 = t ? b1 : a1; int yi1 = t ? j1 : i1;
    bool u = ltlex(x0, xi0, y0, yi0);
    float o1 = u ? x0 : y0; int oi1 = u ? xi0 : yi0;
    float z0 = u ? x1 : y1; int zi0 = u ? xi1 : yi1;
    float z1 = u ? y0 : x0; int zi1 = u ? yi0 : xi0;
    bool v = ltlex(z0, zi0, z1, zi1);
    a0 = o0; a1 = o1; a2 = v ? z0 : z1;
    i0 = oi0; i1 = oi1; i2 = v ? zi0 : zi1;
}

// ---------------------------------------------------------------------------
// Single-pass exact 3-NN over M candidates + inverse-distance weighted g-sum.
template <int M>
__device__ __forceinline__ void scale_nn(
    const float* __restrict__ coord, const float* __restrict__ gsrc,
    const Q4& q, int tid, int split,
    ulonglong2* s_ab, ulonglong2* s_cd, float* pred) {
    float D0[QPT], D1[QPT], D2[QPT];
    int   I0[QPT], I1[QPT], I2[QPT];
#pragma unroll
    for (int j = 0; j < QPT; ++j) {
        D0[j] = D1[j] = D2[j] = INF_F;
        I0[j] = I1[j] = I2[j] = 0x7fffffff;
    }

    for (int t0 = 0; t0 < M; t0 += TILE) {
        __syncthreads();
        fill_tile(coord, t0, s_ab, s_cd, tid);
        __syncthreads();
#pragma unroll 4
        for (int i = 0; i < TILE / SPLIT; ++i) {
            int loc = (i << 3) | split;
            ulonglong2 AB = s_ab[loc];
            ulonglong2 CD = s_cd[loc];
            ull dd01 = d2q(AB.x, AB.y, CD.x, CD.y, q.x01, q.y01, q.z01, q.s01);
            ull dd23 = d2q(AB.x, AB.y, CD.x, CD.y, q.x23, q.y23, q.z23, q.s23);
            float e0, e1, e2, e3;
            f2unpack(e0, e1, dd01);
            f2unpack(e2, e3, dd23);
            // one branch region per candidate (chained FSETP.OR)
            if ((e0 < D2[0]) | (e1 < D2[1]) | (e2 < D2[2]) | (e3 < D2[3])) {
                int ib = t0 + loc;
                if (e0 < D2[0]) ins3(e0, ib, D0[0], D1[0], D2[0], I0[0], I1[0], I2[0]);
                if (e1 < D2[1]) ins3(e1, ib, D0[1], D1[1], D2[1], I0[1], I1[1], I2[1]);
                if (e2 < D2[2]) ins3(e2, ib, D0[2], D1[2], D2[2], I0[2], I1[2], I2[2]);
                if (e3 < D2[3]) ins3(e3, ib, D0[3], D1[3], D2[3], I0[3], I1[3], I2[3]);
            }
        }
    }
#pragma unroll
    for (int j = 0; j < QPT; ++j) {
        float d0 = D0[j], d1 = D1[j], d2 = D2[j];
        int   i0 = I0[j], i1 = I1[j], i2 = I2[j];
#pragma unroll
        for (int off = 1; off < SPLIT; off <<= 1) {
            float b0 = __shfl_xor_sync(0xffffffffu, d0, off);
            float b1 = __shfl_xor_sync(0xffffffffu, d1, off);
            float b2 = __shfl_xor_sync(0xffffffffu, d2, off);
            int   j0 = __shfl_xor_sync(0xffffffffu, i0, off);
            int   j1 = __shfl_xor_sync(0xffffffffu, i1, off);
            int   j2 = __shfl_xor_sync(0xffffffffu, i2, off);
            merge3lex(d0, d1, d2, i0, i1, i2, b0, b1, b2, j0, j1, j2);
        }
        float g0 = __ldg(gsrc + i0);
        float g1 = __ldg(gsrc + i1);
        float g2 = __ldg(gsrc + i2);
        float c0 = fmaxf(d0, 0.f), c1 = fmaxf(d1, 0.f), c2 = fmaxf(d2, 0.f);
        float r0 = 1.f / (c0 + 1e-8f);
        float r1 = 1.f / (c1 + 1e-8f);
        float r2 = 1.f / (c2 + 1e-8f);
        float S  = __fadd_rn(__fadd_rn(r0, r1), r2);
        float w0 = r0 / S, w1 = r1 / S, w2 = r2 / S;
        pred[j] += __fadd_rn(__fadd_rn(__fmul_rn(w0, g0), __fmul_rn(w1, g1)),
                             __fmul_rn(w2, g2));
    }
}

// ---------------------------------------------------------------------------
// Mask: exact reference-rounded min of d2 (branch-free)
template <int M>
__device__ __forceinline__ void mask_min(
    const float* __restrict__ coord, const Q4& q, int tid, int split,
    ulonglong2* s_ab, ulonglong2* s_cd, float* mind) {
    float m[QPT];
#pragma unroll
    for (int j = 0; j < QPT; ++j) m[j] = INF_F;

    for (int t0 = 0; t0 < M; t0 += TILE) {
        __syncthreads();
        fill_tile(coord, t0, s_ab, s_cd, tid);
        __syncthreads();
#pragma unroll 4
        for (int i = 0; i < TILE / SPLIT; ++i) {
            int loc = (i << 3) | split;
            ulonglong2 AB = s_ab[loc];
            ulonglong2 CD = s_cd[loc];
            ull dd01 = d2q(AB.x, AB.y, CD.x, CD.y, q.x01, q.y01, q.z01, q.s01);
            ull dd23 = d2q(AB.x, AB.y, CD.x, CD.y, q.x23, q.y23, q.z23, q.s23);
            float e0, e1, e2, e3;
            f2unpack(e0, e1, dd01);
            f2unpack(e2, e3, dd23);
            m[0] = fminf(m[0], e0);
            m[1] = fminf(m[1], e1);
            m[2] = fminf(m[2], e2);
            m[3] = fminf(m[3], e3);
        }
    }
#pragma unroll
    for (int j = 0; j < QPT; ++j)
#pragma unroll
        for (int off = 1; off < SPLIT; off <<= 1)
            m[j] = fminf(m[j], __shfl_xor_sync(0xffffffffu, m[j], off));
#pragma unroll
    for (int j = 0; j < QPT; ++j) mind[j] = m[j];
}

// ---------------------------------------------------------------------------
__global__ __launch_bounds__(TPB)
void height_compression_main(const float* __restrict__ pts,
                             const float* __restrict__ k2,
                             const float* __restrict__ k3,
                             const float* __restrict__ k4,
                             const float* __restrict__ mp,
                             float* __restrict__ out) {
    __shared__ ulonglong2 s_ab[TILE];   // (x,x),(y,y)   16KB
    __shared__ ulonglong2 s_cd[TILE];   // (z,z),(Sk,Sk) 16KB

    const int tid   = threadIdx.x;
    const int split = tid & (SPLIT - 1);
    const int qg    = tid >> 3;
    const int q0    = blockIdx.x * QPB + qg * QPT;
    const int b     = blockIdx.x >> 6;   // 64 blocks per batch (QPB=128)

    Q4 q;
    {
        float qx[QPT], qy[QPT], qz[QPT], qs[QPT];
#pragma unroll
        for (int j = 0; j < QPT; ++j) {
            qx[j] = pts[(q0 + j) * 3 + 0];
            qy[j] = pts[(q0 + j) * 3 + 1];
            qz[j] = pts[(q0 + j) * 3 + 2];
            qs[j] = norm2_ref(qx[j], qy[j], qz[j]);
        }
        q.x01 = f2pack(qx[0], qx[1]); q.x23 = f2pack(qx[2], qx[3]);
        q.y01 = f2pack(qy[0], qy[1]); q.y23 = f2pack(qy[2], qy[3]);
        q.z01 = f2pack(qz[0], qz[1]); q.z23 = f2pack(qz[2], qz[3]);
        q.s01 = f2pack(qs[0], qs[1]); q.s23 = f2pack(qs[2], qs[3]);
    }

    float pred[QPT] = {0.f, 0.f, 0.f, 0.f};

    scale_nn<M2_>(k2 + (size_t)b * M2_ * 3, d_g + (size_t)b * M2_,
                  q, tid, split, s_ab, s_cd, pred);
    scale_nn<M3_>(k3 + (size_t)b * M3_ * 3, d_g + B_ * M2_ + (size_t)b * M3_,
                  q, tid, split, s_ab, s_cd, pred);
    scale_nn<M4_>(k4 + (size_t)b * M4_ * 3,
                  d_g + B_ * (M2_ + M3_) + (size_t)b * M4_,
                  q, tid, split, s_ab, s_cd, pred);

    float mind[QPT];
    mask_min<MM_>(mp + (size_t)b * MM_ * 3, q, tid, split, s_ab, s_cd, mind);

    if (split == 0) {
#pragma unroll
        for (int j = 0; j < QPT; ++j) {
            out[q0 + j] = pred[j];
            float md = sqrtf(fmaxf(mind[j], 0.f));   // ref: sqrt then < 0.5
            out[BN_ + q0 + j] = (md < 0.5f) ? 1.0f : 0.0f;
        }
    }
}

// ---------------------------------------------------------------------------
extern "C" void kernel_launch(void* const* d_in, const int* in_sizes, int n_in,
                              void* d_out, int out_size) {
    const float* pts  = (const float*)d_in[0];
    const float* k2   = (const float*)d_in[1];
    const float* f2   = (const float*)d_in[2];
    const float* k3   = (const float*)d_in[3];
    const float* f3   = (const float*)d_in[4];
    const float* k4   = (const float*)d_in[5];
    const float* f4   = (const float*)d_in[6];
    const float* mp   = (const float*)d_in[7];
    const float* wfc  = (const float*)d_in[8];
    const float* wcls = (const float*)d_in[9];

    // 4*(8192+4096+2048) = 57344 points, 32 points/block
    compute_gv_kernel<<<57344 / 32, 1024>>>(f2, f3, f4, wfc, wcls);
    height_compression_main<<<BN_ / QPB, TPB>>>(pts, k2, k3, k4, mp,
                                                (float*)d_out);
}